// round 9
// baseline (speedup 1.0000x reference)
#include <cuda_runtime.h>
#include <cuda_bf16.h>
#include <cstdint>

// Problem constants
#define BB 16
#define KK 256
#define ZZ 128
#define HH 128
#define NROWS (BB * KK)   // 4096

// Scratch (device globals — no allocation allowed)
__device__ __align__(16) float g_m1z[NROWS * ZZ];
__device__ __align__(16) float g_m2z[NROWS * ZZ];
__device__ __align__(16) float g_m  [NROWS * ZZ];

// ---------------------------------------------------------------------------
// K1: y=0: m1z = z @ W1^T + b1 ;  y=1: m2z = z @ W2^T + b2
// grid (256, 2), 256 threads. Block = 16 rows x 128 c, one weight matrix.
// smem: zs 8KB + wt 10KB = 18KB; low regs -> 3-4 blocks/SM resident.
// wt row stride 20 floats => conflict-free LDS.128 in 8-lane phases.
// ---------------------------------------------------------------------------
__global__ __launch_bounds__(256, 4) void k1_gemm(
    const float* __restrict__ z,
    const float* __restrict__ W1, const float* __restrict__ b1,
    const float* __restrict__ W2, const float* __restrict__ b2)
{
    const float* __restrict__ W    = blockIdx.y ? W2 : W1;
    const float* __restrict__ bias = blockIdx.y ? b2 : b1;
    float*       __restrict__ dst  = blockIdx.y ? g_m2z : g_m1z;

    __shared__ __align__(16) float zs[16 * 128];   // [r][k]
    __shared__ __align__(16) float wt[128 * 20];   // [c][kk], 16-k chunk

    const int tid  = threadIdx.x;
    const int c    = tid & 127;
    const int ty   = tid >> 7;             // 0/1 -> 8 rows each
    const int row0 = blockIdx.x * 16;

    for (int idx = tid; idx < 16 * 128; idx += 256)
        zs[idx] = z[row0 * 128 + idx];

    float acc[8];
#pragma unroll
    for (int r = 0; r < 8; r++) acc[r] = 0.f;

    for (int k0 = 0; k0 < 128; k0 += 16) {
        __syncthreads();
        for (int idx = tid; idx < 2048; idx += 256) {
            int cc = idx >> 4, kk = idx & 15;
            wt[cc * 20 + kk] = W[cc * 128 + k0 + kk];
        }
        __syncthreads();

#pragma unroll
        for (int k4 = 0; k4 < 16; k4 += 4) {
            float4 w = *(const float4*)&wt[c * 20 + k4];
#pragma unroll
            for (int r = 0; r < 8; r++) {
                float4 zv = *(const float4*)&zs[(ty * 8 + r) * 128 + k0 + k4];
                acc[r] += zv.x * w.x; acc[r] += zv.y * w.y;
                acc[r] += zv.z * w.z; acc[r] += zv.w * w.w;
            }
        }
    }

    const float bb = bias[c];
#pragma unroll
    for (int r = 0; r < 8; r++) {
        int row = row0 + ty * 8 + r;
        dst[row * 128 + c] = acc[r] + bb;
    }
}

// ---------------------------------------------------------------------------
// K2: g_m[b,i,c] = relu(m1z[b,i,c] + max_{j : P[b,j,i]!=0} m2z[b,j,c])
// grid (16 i-tiles, 16 batches), 256 threads.
//   c4 = tid&31 -> channels 4*c4..4*c4+3 ; sg = tid>>5 -> i = i0+sg*2+{0,1}
// m2z rows staged through shared in 32-j chunks (16KB) -> LDS instead of
// dependent L2 LDGs. Mask bits warp-uniform -> predicated FMNMX.
// ---------------------------------------------------------------------------
__global__ __launch_bounds__(256) void k2_maskmax(const int* __restrict__ P)
{
    __shared__ unsigned smask[256];                 // low 16 bits used
    __shared__ __align__(16) float4 sj[32 * 32];    // 32 j-rows x 128 c, 16KB

    const int tid  = threadIdx.x;
    const int b    = blockIdx.y;
    const int i0   = blockIdx.x * 16;
    const int lane = tid & 31;
    const int wrp  = tid >> 5;          // 0..7

    // bit t of smask[j] = (P[b, j, i0+t] != 0); one ballot covers 2 j rows
    for (int jp = wrp; jp < 128; jp += 8) {
        int j  = 2 * jp + (lane >> 4);
        int io = lane & 15;
        int v  = P[((b * 256 + j) * 256) + i0 + io];
        unsigned word = __ballot_sync(0xffffffffu, v != 0);
        if (lane == 0) {
            smask[2 * jp]     = word & 0xffffu;
            smask[2 * jp + 1] = word >> 16;
        }
    }

    const int c4 = tid & 31;
    const int sg = tid >> 5;

    float4 mx0 = make_float4(-3.0e38f, -3.0e38f, -3.0e38f, -3.0e38f);
    float4 mx1 = mx0;

    const float4* m2 = (const float4*)g_m2z + (size_t)b * 256 * 32;

    for (int j0 = 0; j0 < 256; j0 += 32) {
        __syncthreads();                 // first iter: also fences smask
        for (int t = tid; t < 1024; t += 256)
            sj[t] = m2[j0 * 32 + t];
        __syncthreads();

#pragma unroll
        for (int jj = 0; jj < 32; jj++) {
            float4 v = sj[jj * 32 + c4];
            unsigned mw = smask[j0 + jj] >> (sg * 2);
            if (mw & 1u) {
                mx0.x = fmaxf(mx0.x, v.x); mx0.y = fmaxf(mx0.y, v.y);
                mx0.z = fmaxf(mx0.z, v.z); mx0.w = fmaxf(mx0.w, v.w);
            }
            if (mw & 2u) {
                mx1.x = fmaxf(mx1.x, v.x); mx1.y = fmaxf(mx1.y, v.y);
                mx1.z = fmaxf(mx1.z, v.z); mx1.w = fmaxf(mx1.w, v.w);
            }
        }
    }

    const float4* m1 = (const float4*)g_m1z + (size_t)b * 256 * 32;
    float4*       gm = (float4*)g_m        + (size_t)b * 256 * 32;

    {
        int i = i0 + sg * 2;
        float4 a = m1[i * 32 + c4];
        float4 o;
        o.x = fmaxf(a.x + mx0.x, 0.f); o.y = fmaxf(a.y + mx0.y, 0.f);
        o.z = fmaxf(a.z + mx0.z, 0.f); o.w = fmaxf(a.w + mx0.w, 0.f);
        gm[i * 32 + c4] = o;
    }
    {
        int i = i0 + sg * 2 + 1;
        float4 a = m1[i * 32 + c4];
        float4 o;
        o.x = fmaxf(a.x + mx1.x, 0.f); o.y = fmaxf(a.y + mx1.y, 0.f);
        o.z = fmaxf(a.z + mx1.z, 0.f); o.w = fmaxf(a.w + mx1.w, 0.f);
        gm[i * 32 + c4] = o;
    }
}

// ---------------------------------------------------------------------------
// K3: out[row,h] = relu(bu[h] + sum_{f<128} z[row,f]*Wu[h,f]
//                              + sum_{f>=128} m[row,f-128]*Wu[h,f])
// grid (256 row-tiles, 2 h-halves), 256 threads.
// Block = 64 h x 16 rows, K = 256 in 16-k chunks.
//   hl = tid&63 -> h = h0+hl ; ty = tid>>6 (0..3) -> 4 rows each.
// ---------------------------------------------------------------------------
__global__ __launch_bounds__(256, 4) void k3_out(
    const float* __restrict__ z,
    const float* __restrict__ Wu, const float* __restrict__ bu,
    float* __restrict__ out)
{
    __shared__ __align__(16) float wt[64 * 20];   // [hl][kk], 5KB
    __shared__ __align__(16) float xs[16 * 16];   // [r][kk],  1KB

    const int tid  = threadIdx.x;
    const int hl   = tid & 63;
    const int ty   = tid >> 6;            // 0..3 -> 4 rows each
    const int h0   = blockIdx.y * 64;
    const int row0 = blockIdx.x * 16;

    float acc[4];
#pragma unroll
    for (int r = 0; r < 4; r++) acc[r] = 0.f;

    for (int k0 = 0; k0 < 256; k0 += 16) {
        __syncthreads();
        // stage Wu chunk: 64 h x 16 kk = 1024 elems
        for (int idx = tid; idx < 1024; idx += 256) {
            int hh = idx >> 4, kk = idx & 15;
            wt[hh * 20 + kk] = Wu[(h0 + hh) * 256 + k0 + kk];
        }
        // stage x chunk: 16 rows x 16 kk = 256 elems
        if (tid < 256) {
            int r = tid >> 4, kk = tid & 15;
            int f = k0 + kk;
            int row = row0 + r;
            xs[r * 16 + kk] = (f < 128) ? z[row * 128 + f]
                                        : g_m[row * 128 + f - 128];
        }
        __syncthreads();

#pragma unroll
        for (int k4 = 0; k4 < 16; k4 += 4) {
            float4 w = *(const float4*)&wt[hl * 20 + k4];
#pragma unroll
            for (int r = 0; r < 4; r++) {
                float4 x = *(const float4*)&xs[(ty * 4 + r) * 16 + k4];
                acc[r] += x.x * w.x; acc[r] += x.y * w.y;
                acc[r] += x.z * w.z; acc[r] += x.w * w.w;
            }
        }
    }

    const float bb = bu[h0 + hl];
#pragma unroll
    for (int r = 0; r < 4; r++) {
        int row = row0 + ty * 4 + r;
        out[row * 128 + h0 + hl] = fmaxf(acc[r] + bb, 0.f);
    }
}

// ---------------------------------------------------------------------------
// Launch. Inputs (metadata order): z, P, W1, b1, W2, b2, Wu, bu.
// Output: [B, K, H] float32 = 524288 elements.
// ---------------------------------------------------------------------------
extern "C" void kernel_launch(void* const* d_in, const int* in_sizes, int n_in,
                              void* d_out, int out_size)
{
    const float* z  = (const float*)d_in[0];
    const int*   P  = (const int*)  d_in[1];
    const float* W1 = (const float*)d_in[2];
    const float* b1 = (const float*)d_in[3];
    const float* W2 = (const float*)d_in[4];
    const float* b2 = (const float*)d_in[5];
    const float* Wu = (const float*)d_in[6];
    const float* bu = (const float*)d_in[7];
    float* out = (float*)d_out;

    dim3 g1(NROWS / 16, 2);   // (256, 2)
    k1_gemm<<<g1, 256>>>(z, W1, b1, W2, b2);

    dim3 g2(KK / 16, BB);     // (16, 16)
    k2_maskmax<<<g2, 256>>>(P);

    dim3 g3(NROWS / 16, 2);   // (256, 2)
    k3_out<<<g3, 256>>>(z, Wu, bu, out);
}

// round 11
// speedup vs baseline: 1.3901x; 1.3901x over previous
#include <cuda_runtime.h>
#include <cuda_bf16.h>
#include <cstdint>

// Problem constants
#define BB 16
#define KK 256
#define ZZ 128
#define HH 128
#define NROWS (BB * KK)   // 4096

// fp32 scratch (K2 inputs)
__device__ __align__(16) float g_m1z[NROWS * ZZ];
__device__ __align__(16) float g_m2z[NROWS * ZZ];

// bf16x2-packed hi/lo operands (u32 = 2 bf16 along k)
__device__ __align__(16) unsigned g_z2hi [NROWS * 64];    // z  [4096][64]
__device__ __align__(16) unsigned g_z2lo [NROWS * 64];
__device__ __align__(16) unsigned g_w2hi [256 * 64];      // [W1;W2] [256][64]
__device__ __align__(16) unsigned g_w2lo [256 * 64];
__device__ __align__(16) unsigned g_wu2hi[128 * 128];     // Wu [128][128]
__device__ __align__(16) unsigned g_wu2lo[128 * 128];
__device__ __align__(16) unsigned g_x2hi [NROWS * 128];   // X=[z|m] [4096][128]
__device__ __align__(16) unsigned g_x2lo [NROWS * 128];

// ---------------------------------------------------------------------------
// helpers
// ---------------------------------------------------------------------------
__device__ __forceinline__ void split2(float x0, float x1,
                                       unsigned &hi, unsigned &lo)
{
    float2 v = make_float2(x0, x1);
    __nv_bfloat162 h = __float22bfloat162_rn(v);
    float2 hf = __bfloat1622float2(h);
    __nv_bfloat162 l = __float22bfloat162_rn(make_float2(v.x - hf.x, v.y - hf.y));
    hi = *reinterpret_cast<unsigned*>(&h);
    lo = *reinterpret_cast<unsigned*>(&l);
}

__device__ __forceinline__ void mma_bf16(float c[4],
    unsigned a0, unsigned a1, unsigned a2, unsigned a3,
    unsigned b0, unsigned b1)
{
    asm volatile(
        "mma.sync.aligned.m16n8k16.row.col.f32.bf16.bf16.f32 "
        "{%0,%1,%2,%3}, {%4,%5,%6,%7}, {%8,%9}, {%0,%1,%2,%3};"
        : "+f"(c[0]), "+f"(c[1]), "+f"(c[2]), "+f"(c[3])
        : "r"(a0), "r"(a1), "r"(a2), "r"(a3), "r"(b0), "r"(b1));
}

// ---------------------------------------------------------------------------
// P0: split z, [W1;W2], Wu into bf16x2 hi/lo. One float2 task per thread.
//   tasks: z 262144, Wcat 16384, Wu 16384  -> 294912 = 1152 * 256
// ---------------------------------------------------------------------------
__global__ __launch_bounds__(256) void p0_split(
    const float* __restrict__ z,
    const float* __restrict__ W1, const float* __restrict__ W2,
    const float* __restrict__ Wu)
{
    int idx = blockIdx.x * 256 + threadIdx.x;
    if (idx < NROWS * 64) {
        float2 v = ((const float2*)z)[idx];
        unsigned hi, lo; split2(v.x, v.y, hi, lo);
        g_z2hi[idx] = hi; g_z2lo[idx] = lo;
        int row = idx >> 6, kp = idx & 63;
        g_x2hi[row * 128 + kp] = hi; g_x2lo[row * 128 + kp] = lo;
    } else if (idx < NROWS * 64 + 256 * 64) {
        int i = idx - NROWS * 64;
        int n = i >> 6, kp = i & 63;
        const float* Wr = (n < 128) ? (W1 + n * 128) : (W2 + (n - 128) * 128);
        unsigned hi, lo; split2(Wr[2 * kp], Wr[2 * kp + 1], hi, lo);
        g_w2hi[i] = hi; g_w2lo[i] = lo;
    } else if (idx < NROWS * 64 + 256 * 64 + 128 * 128) {
        int i = idx - NROWS * 64 - 256 * 64;
        int h = i >> 7, kp = i & 127;
        unsigned hi, lo; split2(Wu[h * 256 + 2 * kp], Wu[h * 256 + 2 * kp + 1], hi, lo);
        g_wu2hi[i] = hi; g_wu2lo[i] = lo;
    }
}

// ---------------------------------------------------------------------------
// K1': [m1z | m2z] = z @ [W1;W2]^T + bias   via 3-pass bf16 split mma.
// grid (64 row-blocks, 4 n-bands of 64), 128 threads = 4 warps (2m x 2n),
// warp tile 32x32 = 2 mtiles x 4 ntiles of m16n8k16, K = 128 (8 ksteps).
// Fragments loaded directly from L1-resident packed globals (no smem).
// ---------------------------------------------------------------------------
__global__ __launch_bounds__(128) void k1_mma(
    const float* __restrict__ b1, const float* __restrict__ b2)
{
    const int lane = threadIdx.x & 31;
    const int wid  = threadIdx.x >> 5;
    const int wm   = wid >> 1, wn = wid & 1;
    const int g    = lane >> 2, t = lane & 3;
    const int row0 = blockIdx.x * 64 + wm * 32;
    const int n0   = blockIdx.y * 64 + wn * 32;

    float c[2][4][4];
#pragma unroll
    for (int mt = 0; mt < 2; mt++)
#pragma unroll
        for (int nt = 0; nt < 4; nt++)
#pragma unroll
            for (int q = 0; q < 4; q++) c[mt][nt][q] = 0.f;

#pragma unroll 2
    for (int ks = 0; ks < 8; ks++) {
        const int kp0 = ks * 8;
        unsigned ah[2][4], al[2][4], bh[4][2], bl[4][2];
#pragma unroll
        for (int mt = 0; mt < 2; mt++) {
            int ra = (row0 + mt * 16 + g) * 64 + kp0 + t;
            int rb = (row0 + mt * 16 + g + 8) * 64 + kp0 + t;
            ah[mt][0] = g_z2hi[ra];     ah[mt][1] = g_z2hi[rb];
            ah[mt][2] = g_z2hi[ra + 4]; ah[mt][3] = g_z2hi[rb + 4];
            al[mt][0] = g_z2lo[ra];     al[mt][1] = g_z2lo[rb];
            al[mt][2] = g_z2lo[ra + 4]; al[mt][3] = g_z2lo[rb + 4];
        }
#pragma unroll
        for (int nt = 0; nt < 4; nt++) {
            int nb = (n0 + nt * 8 + g) * 64 + kp0 + t;
            bh[nt][0] = g_w2hi[nb]; bh[nt][1] = g_w2hi[nb + 4];
            bl[nt][0] = g_w2lo[nb]; bl[nt][1] = g_w2lo[nb + 4];
        }
#pragma unroll
        for (int mt = 0; mt < 2; mt++)
#pragma unroll
            for (int nt = 0; nt < 4; nt++) {
                mma_bf16(c[mt][nt], ah[mt][0], ah[mt][1], ah[mt][2], ah[mt][3],
                         bh[nt][0], bh[nt][1]);
                mma_bf16(c[mt][nt], ah[mt][0], ah[mt][1], ah[mt][2], ah[mt][3],
                         bl[nt][0], bl[nt][1]);
                mma_bf16(c[mt][nt], al[mt][0], al[mt][1], al[mt][2], al[mt][3],
                         bh[nt][0], bh[nt][1]);
            }
    }

    const bool second = (blockIdx.y >= 2);
    float* __restrict__ dst = second ? g_m2z : g_m1z;
    const float* __restrict__ bias = second ? b2 : b1;
    const int nbase = second ? (n0 - 128) : n0;

#pragma unroll
    for (int mt = 0; mt < 2; mt++)
#pragma unroll
        for (int nt = 0; nt < 4; nt++) {
            int n = nbase + nt * 8 + 2 * t;
            float bv0 = bias[n], bv1 = bias[n + 1];
            int r = row0 + mt * 16 + g;
            dst[r * 128 + n]           = c[mt][nt][0] + bv0;
            dst[r * 128 + n + 1]       = c[mt][nt][1] + bv1;
            dst[(r + 8) * 128 + n]     = c[mt][nt][2] + bv0;
            dst[(r + 8) * 128 + n + 1] = c[mt][nt][3] + bv1;
        }
}

// ---------------------------------------------------------------------------
// K2: relu(m1z[b,i,c] + max_{j:P[b,j,i]!=0} m2z[b,j,c]); writes bf16 hi/lo
// message half of X. grid (16 i-tiles, 16 batches), 256 threads.
//   c4 = tid&31 -> 4 channels ; sg = tid>>5 -> i = i0+sg*2+{0,1}
// ---------------------------------------------------------------------------
__global__ __launch_bounds__(256) void k2_maskmax(const int* __restrict__ P)
{
    __shared__ unsigned smask[256];   // low 16 bits used

    const int tid  = threadIdx.x;
    const int b    = blockIdx.y;
    const int i0   = blockIdx.x * 16;
    const int lane = tid & 31;
    const int wrp  = tid >> 5;

    for (int jp = wrp; jp < 128; jp += 8) {
        int j  = 2 * jp + (lane >> 4);
        int io = lane & 15;
        int v  = P[((b * 256 + j) * 256) + i0 + io];
        unsigned word = __ballot_sync(0xffffffffu, v != 0);
        if (lane == 0) {
            smask[2 * jp]     = word & 0xffffu;
            smask[2 * jp + 1] = word >> 16;
        }
    }
    __syncthreads();

    const int c4 = tid & 31;
    const int sg = tid >> 5;

    float4 mx0 = make_float4(-3.0e38f, -3.0e38f, -3.0e38f, -3.0e38f);
    float4 mx1 = mx0;

    const float4* m2 = (const float4*)g_m2z + (size_t)b * 256 * 32;

#pragma unroll 4
    for (int j = 0; j < 256; j++) {
        float4 v = m2[j * 32 + c4];
        unsigned mw = smask[j] >> (sg * 2);
        if (mw & 1u) {
            mx0.x = fmaxf(mx0.x, v.x); mx0.y = fmaxf(mx0.y, v.y);
            mx0.z = fmaxf(mx0.z, v.z); mx0.w = fmaxf(mx0.w, v.w);
        }
        if (mw & 2u) {
            mx1.x = fmaxf(mx1.x, v.x); mx1.y = fmaxf(mx1.y, v.y);
            mx1.z = fmaxf(mx1.z, v.z); mx1.w = fmaxf(mx1.w, v.w);
        }
    }

    const float4* m1 = (const float4*)g_m1z + (size_t)b * 256 * 32;

#pragma unroll
    for (int s = 0; s < 2; s++) {
        int i = i0 + sg * 2 + s;
        float4 mxv = s ? mx1 : mx0;
        float4 a = m1[i * 32 + c4];
        float4 o;
        o.x = fmaxf(a.x + mxv.x, 0.f); o.y = fmaxf(a.y + mxv.y, 0.f);
        o.z = fmaxf(a.z + mxv.z, 0.f); o.w = fmaxf(a.w + mxv.w, 0.f);

        int grow = b * 256 + i;
        unsigned h0, l0, h1, l1;
        split2(o.x, o.y, h0, l0);
        split2(o.z, o.w, h1, l1);
        int base = grow * 128 + 64 + 2 * c4;
        g_x2hi[base]     = h0; g_x2hi[base + 1] = h1;
        g_x2lo[base]     = l0; g_x2lo[base + 1] = l1;
    }
}

// ---------------------------------------------------------------------------
// K3': out = relu(X @ Wu^T + bu), X = [z | m] (pre-split bf16 hi/lo), K=256.
// grid (64, 2), 128 threads, same warp tiling as K1'. 16 ksteps.
// ---------------------------------------------------------------------------
__global__ __launch_bounds__(128) void k3_mma(
    const float* __restrict__ bu, float* __restrict__ out)
{
    const int lane = threadIdx.x & 31;
    const int wid  = threadIdx.x >> 5;
    const int wm   = wid >> 1, wn = wid & 1;
    const int g    = lane >> 2, t = lane & 3;
    const int row0 = blockIdx.x * 64 + wm * 32;
    const int n0   = blockIdx.y * 64 + wn * 32;

    float c[2][4][4];
#pragma unroll
    for (int mt = 0; mt < 2; mt++)
#pragma unroll
        for (int nt = 0; nt < 4; nt++)
#pragma unroll
            for (int q = 0; q < 4; q++) c[mt][nt][q] = 0.f;

#pragma unroll 2
    for (int ks = 0; ks < 16; ks++) {
        const int kp0 = ks * 8;
        unsigned ah[2][4], al[2][4], bh[4][2], bl[4][2];
#pragma unroll
        for (int mt = 0; mt < 2; mt++) {
            int ra = (row0 + mt * 16 + g) * 128 + kp0 + t;
            int rb = (row0 + mt * 16 + g + 8) * 128 + kp0 + t;
            ah[mt][0] = g_x2hi[ra];     ah[mt][1] = g_x2hi[rb];
            ah[mt][2] = g_x2hi[ra + 4]; ah[mt][3] = g_x2hi[rb + 4];
            al[mt][0] = g_x2lo[ra];     al[mt][1] = g_x2lo[rb];
            al[mt][2] = g_x2lo[ra + 4]; al[mt][3] = g_x2lo[rb + 4];
        }
#pragma unroll
        for (int nt = 0; nt < 4; nt++) {
            int nb = (n0 + nt * 8 + g) * 128 + kp0 + t;
            bh[nt][0] = g_wu2hi[nb]; bh[nt][1] = g_wu2hi[nb + 4];
            bl[nt][0] = g_wu2lo[nb]; bl[nt][1] = g_wu2lo[nb + 4];
        }
#pragma unroll
        for (int mt = 0; mt < 2; mt++)
#pragma unroll
            for (int nt = 0; nt < 4; nt++) {
                mma_bf16(c[mt][nt], ah[mt][0], ah[mt][1], ah[mt][2], ah[mt][3],
                         bh[nt][0], bh[nt][1]);
                mma_bf16(c[mt][nt], ah[mt][0], ah[mt][1], ah[mt][2], ah[mt][3],
                         bl[nt][0], bl[nt][1]);
                mma_bf16(c[mt][nt], al[mt][0], al[mt][1], al[mt][2], al[mt][3],
                         bh[nt][0], bh[nt][1]);
            }
    }

#pragma unroll
    for (int mt = 0; mt < 2; mt++)
#pragma unroll
        for (int nt = 0; nt < 4; nt++) {
            int n = n0 + nt * 8 + 2 * t;
            float bv0 = bu[n], bv1 = bu[n + 1];
            int r = row0 + mt * 16 + g;
            out[r * 128 + n]           = fmaxf(c[mt][nt][0] + bv0, 0.f);
            out[r * 128 + n + 1]       = fmaxf(c[mt][nt][1] + bv1, 0.f);
            out[(r + 8) * 128 + n]     = fmaxf(c[mt][nt][2] + bv0, 0.f);
            out[(r + 8) * 128 + n + 1] = fmaxf(c[mt][nt][3] + bv1, 0.f);
        }
}

// ---------------------------------------------------------------------------
// Launch. Inputs (metadata order): z, P, W1, b1, W2, b2, Wu, bu.
// ---------------------------------------------------------------------------
extern "C" void kernel_launch(void* const* d_in, const int* in_sizes, int n_in,
                              void* d_out, int out_size)
{
    const float* z  = (const float*)d_in[0];
    const int*   P  = (const int*)  d_in[1];
    const float* W1 = (const float*)d_in[2];
    const float* b1 = (const float*)d_in[3];
    const float* W2 = (const float*)d_in[4];
    const float* b2 = (const float*)d_in[5];
    const float* Wu = (const float*)d_in[6];
    const float* bu = (const float*)d_in[7];
    float* out = (float*)d_out;

    p0_split<<<1152, 256>>>(z, W1, W2, Wu);

    dim3 g1(64, 4);
    k1_mma<<<g1, 128>>>(b1, b2);

    dim3 g2(16, 16);
    k2_maskmax<<<g2, 256>>>(P);

    dim3 g3(64, 2);
    k3_mma<<<g3, 128>>>(bu, out);
}